// round 14
// baseline (speedup 1.0000x reference)
#include <cuda_runtime.h>
#include <cuda_bf16.h>
#include <cstdint>

#define NN 100000
#define EE 1600000
#define DD 128

// Scratch (allocation-free rule: __device__ globals)
__device__ float g_h   [NN * DD];
__device__ float g_h2  [NN * DD];
__device__ int   g_src [EE];
__device__ int   g_dst [EE];
__device__ int   g_esrc[EE];
__device__ int   g_degi[NN];
__device__ int   g_rowptr[NN + 1];
__device__ int   g_cursor[NN];
__device__ int   g_bsum[128];
__device__ int   g_boff[128];
__device__ int   g_is64;

// ===========================================================================
// PTX helpers (sm_80-compatible only: ldmatrix + mma.sync; NO tcgen05 — the
// harness compiles PTX at target compute_103, which rejects 'a' features)
// ===========================================================================
__device__ __forceinline__ uint32_t smem_u32(const void* p) {
    uint32_t a;
    asm("{ .reg .u64 t; cvta.to.shared.u64 t, %1; cvt.u32.u64 %0, t; }"
        : "=r"(a) : "l"(p));
    return a;
}
__device__ __forceinline__ void ldsm_x4(uint32_t* r, uint32_t addr) {
    asm volatile("ldmatrix.sync.aligned.m8n8.x4.shared.b16 {%0,%1,%2,%3}, [%4];"
                 : "=r"(r[0]), "=r"(r[1]), "=r"(r[2]), "=r"(r[3]) : "r"(addr));
}
__device__ __forceinline__ void mma16816(float* d, const uint32_t* a,
                                         const uint32_t* b) {
    asm volatile(
        "mma.sync.aligned.m16n8k16.row.col.f32.bf16.bf16.f32 "
        "{%0,%1,%2,%3}, {%4,%5,%6,%7}, {%8,%9}, {%0,%1,%2,%3};"
        : "+f"(d[0]), "+f"(d[1]), "+f"(d[2]), "+f"(d[3])
        : "r"(a[0]), "r"(a[1]), "r"(a[2]), "r"(a[3]), "r"(b[0]), "r"(b[1]));
}

// ===========================================================================
// Smem tile layout: bf16 [128][BSTRIDE], BSTRIDE=136.
// lin:  A_hi, A_lo, B_hi, B_lo           (4 regions, 139264 B)
// sage: A_hi, A_lo, BL_hi, BL_lo, BR_hi, BR_lo (6 regions, 208896 B)
// ===========================================================================
#define BSTRIDE 136
#define W_ELEMS (128 * BSTRIDE)       // 17408 bf16 per hi or lo region
#define TILE_B  (W_ELEMS * 2)         // 34816 bytes
#define R_A_HI  0
#define R_A_LO  (TILE_B)
#define R_B_HI  (2 * TILE_B)
#define LIN_SMEM  (4 * TILE_B)        // 139264
#define SAGE_SMEM (6 * TILE_B)        // 208896
#define GEMM_T   256                  // 8 warps, warp grid 4x2, tile 32x64

// Pre-converted weights: [6 weights][hi 17408 | lo 17408] bf16, smem layout.
__device__ __align__(16) __nv_bfloat16 g_wbf[6 * 2 * W_ELEMS];

// split fp32 pair -> bf16 hi/lo into A regions
__device__ __forceinline__ void cvt_store_pair(char* sm, int r, int c, float2 v) {
    __nv_bfloat16 h0 = __float2bfloat16(v.x);
    __nv_bfloat16 h1 = __float2bfloat16(v.y);
    __nv_bfloat16 l0 = __float2bfloat16(v.x - __bfloat162float(h0));
    __nv_bfloat16 l1 = __float2bfloat16(v.y - __bfloat162float(h1));
    uint32_t off = (uint32_t)(r * BSTRIDE + c) * 2;
    *reinterpret_cast<__nv_bfloat162*>(sm + R_A_HI + off) = __halves2bfloat162(h0, h1);
    *reinterpret_cast<__nv_bfloat162*>(sm + R_A_LO + off) = __halves2bfloat162(l0, l1);
}

// Weight prep: 16 blocks per weight, 256 threads, 4 elems/thread.
__global__ void prep_weights_kernel(const float* __restrict__ w0,
                                    const float* __restrict__ w1,
                                    const float* __restrict__ w2,
                                    const float* __restrict__ w3,
                                    const float* __restrict__ w4,
                                    const float* __restrict__ w5) {
    const float* ws[6] = {w0, w1, w2, w3, w4, w5};
    int w = blockIdx.x >> 4;
    int eb = ((blockIdx.x & 15) << 10) + (threadIdx.x << 2);   // elem base, mult of 4
    float4 v = *reinterpret_cast<const float4*>(ws[w] + eb);
    int r = eb >> 7, c = eb & 127;
    __nv_bfloat16 h0 = __float2bfloat16(v.x);
    __nv_bfloat16 h1 = __float2bfloat16(v.y);
    __nv_bfloat16 h2 = __float2bfloat16(v.z);
    __nv_bfloat16 h3 = __float2bfloat16(v.w);
    __nv_bfloat16 l0 = __float2bfloat16(v.x - __bfloat162float(h0));
    __nv_bfloat16 l1 = __float2bfloat16(v.y - __bfloat162float(h1));
    __nv_bfloat16 l2 = __float2bfloat16(v.z - __bfloat162float(h2));
    __nv_bfloat16 l3 = __float2bfloat16(v.w - __bfloat162float(h3));
    __nv_bfloat16* hi = g_wbf + (size_t)w * 2 * W_ELEMS;
    __nv_bfloat16* lo = hi + W_ELEMS;
    int o = r * BSTRIDE + c;
    *reinterpret_cast<__nv_bfloat162*>(hi + o)     = __halves2bfloat162(h0, h1);
    *reinterpret_cast<__nv_bfloat162*>(hi + o + 2) = __halves2bfloat162(h2, h3);
    *reinterpret_cast<__nv_bfloat162*>(lo + o)     = __halves2bfloat162(l0, l1);
    *reinterpret_cast<__nv_bfloat162*>(lo + o + 2) = __halves2bfloat162(l2, l3);
}

// Copy one pre-converted weight (hi+lo, contiguous 69632 B) into smem.
__device__ __forceinline__ void copy_weight(char* sm, uint32_t dstOff, int widx,
                                            int tid) {
    const uint4* src = reinterpret_cast<const uint4*>(g_wbf + (size_t)widx * 2 * W_ELEMS);
    uint4* dst = reinterpret_cast<uint4*>(sm + dstOff);
    #pragma unroll
    for (int i = 0; i < 17; i++) {
        int idx = tid + i * GEMM_T;
        dst[idx] = src[idx];
    }
}

// Mainloop: warp tile 32x64 (wr 0..3, wc 0..1), 3-term split, accumulate.
// bHi = smem offset of weight hi region; lo is contiguous at bHi + TILE_B.
__device__ __forceinline__ void mma_tile(uint32_t sb, float acc[2][8][4],
                                         int wr, int wc, int l, uint32_t bHi) {
    uint32_t bLo = bHi + TILE_B;
    #pragma unroll 2
    for (int k = 0; k < 8; k++) {
        uint32_t ah0[4], ah1[4], al0[4], al1[4];
        uint32_t arow0 = (uint32_t)(wr * 32 + (l & 15));
        uint32_t acolk = (uint32_t)(k * 16 + (l >> 4) * 8);
        uint32_t aoff0 = (arow0 * BSTRIDE + acolk) * 2;
        uint32_t aoff1 = ((arow0 + 16) * BSTRIDE + acolk) * 2;
        ldsm_x4(ah0, sb + R_A_HI + aoff0);
        ldsm_x4(ah1, sb + R_A_HI + aoff1);
        ldsm_x4(al0, sb + R_A_LO + aoff0);
        ldsm_x4(al1, sb + R_A_LO + aoff1);
        #pragma unroll
        for (int nfp = 0; nfp < 4; nfp++) {
            uint32_t bh4[4], bl4[4];
            uint32_t brow = (uint32_t)(wc * 64 + nfp * 16 + ((l >> 4) & 1) * 8 + (l & 7));
            uint32_t bcol = (uint32_t)(k * 16 + ((l >> 3) & 1) * 8);
            uint32_t boff = (brow * BSTRIDE + bcol) * 2;
            ldsm_x4(bh4, sb + bHi + boff);
            ldsm_x4(bl4, sb + bLo + boff);
            int nf0 = nfp * 2, nf1 = nfp * 2 + 1;
            mma16816(acc[0][nf0], ah0, bh4 + 0);
            mma16816(acc[1][nf0], ah1, bh4 + 0);
            mma16816(acc[0][nf1], ah0, bh4 + 2);
            mma16816(acc[1][nf1], ah1, bh4 + 2);
            mma16816(acc[0][nf0], ah0, bl4 + 0);
            mma16816(acc[1][nf0], ah1, bl4 + 0);
            mma16816(acc[0][nf1], ah0, bl4 + 2);
            mma16816(acc[1][nf1], ah1, bl4 + 2);
            mma16816(acc[0][nf0], al0, bh4 + 0);
            mma16816(acc[1][nf0], al1, bh4 + 0);
            mma16816(acc[0][nf1], al0, bh4 + 2);
            mma16816(acc[1][nf1], al1, bh4 + 2);
        }
    }
}

__device__ __forceinline__ void epilogue(float acc[2][8][4], const float* bias,
                                         float* Y, int rowBase, int wr, int wc,
                                         int l) {
    #pragma unroll
    for (int mf = 0; mf < 2; mf++) {
        #pragma unroll
        for (int nf = 0; nf < 8; nf++) {
            int col = wc * 64 + nf * 8 + (l & 3) * 2;
            float b0 = __ldg(bias + col), b1 = __ldg(bias + col + 1);
            int row0 = rowBase + wr * 32 + mf * 16 + (l >> 2);
            if (row0 < NN) {
                float2 v;
                v.x = fmaxf(acc[mf][nf][0] + b0, 0.f);
                v.y = fmaxf(acc[mf][nf][1] + b1, 0.f);
                *reinterpret_cast<float2*>(Y + (size_t)row0 * DD + col) = v;
            }
            int row1 = row0 + 8;
            if (row1 < NN) {
                float2 v;
                v.x = fmaxf(acc[mf][nf][2] + b0, 0.f);
                v.y = fmaxf(acc[mf][nf][3] + b1, 0.f);
                *reinterpret_cast<float2*>(Y + (size_t)row1 * DD + col) = v;
            }
        }
    }
}

// ===========================================================================
// Edge preprocessing: dtype detect, int32 edge lists, CSR build
// ===========================================================================
__global__ void detect_kernel(const long long* __restrict__ ei) {
    int t = threadIdx.x;
    long long v = ei[(size_t)(t & 15) * (EE / 16) + 3];
    unsigned bad = __ballot_sync(0xFFFFFFFF, v < 0 || v >= NN);
    if (t == 0) g_is64 = (bad == 0) ? 1 : 0;
}

__global__ void zero_degi_kernel() {
    int i = blockIdx.x * blockDim.x + threadIdx.x;
    if (i < NN) g_degi[i] = 0;
}

__global__ void convert_kernel(const void* __restrict__ ei_raw) {
    int e = blockIdx.x * blockDim.x + threadIdx.x;
    if (e >= EE) return;
    int s, d;
    if (g_is64) {
        const long long* ei = (const long long*)ei_raw;
        s = (int)ei[e];
        d = (int)ei[EE + e];
    } else {
        const int* ei = (const int*)ei_raw;
        s = ei[e];
        d = ei[EE + e];
    }
    g_src[e] = s;
    g_dst[e] = d;
    atomicAdd(&g_degi[d], 1);
}

// --- 3-phase parallel exclusive scan over g_degi -> g_rowptr / g_cursor ---
#define SCAN_BT 1024
#define SCAN_NB ((NN + SCAN_BT - 1) / SCAN_BT)   // 98

__global__ void scan_block_kernel() {
    __shared__ int ss[SCAN_BT];
    int t = threadIdx.x;
    int i = blockIdx.x * SCAN_BT + t;
    int v = (i < NN) ? g_degi[i] : 0;
    ss[t] = v;
    __syncthreads();
    for (int d = 1; d < SCAN_BT; d <<= 1) {
        int u = (t >= d) ? ss[t - d] : 0;
        __syncthreads();
        ss[t] += u;
        __syncthreads();
    }
    if (i < NN) g_rowptr[i] = ss[t] - v;   // exclusive within block
    if (t == SCAN_BT - 1) g_bsum[blockIdx.x] = ss[t];
}

__global__ void scan_bsum_kernel() {
    __shared__ int ss[128];
    int t = threadIdx.x;
    int v = (t < SCAN_NB) ? g_bsum[t] : 0;
    ss[t] = v;
    __syncthreads();
    for (int d = 1; d < 128; d <<= 1) {
        int u = (t >= d) ? ss[t - d] : 0;
        __syncthreads();
        ss[t] += u;
        __syncthreads();
    }
    g_boff[t] = ss[t] - v;   // exclusive
}

__global__ void scan_apply_kernel() {
    int i = blockIdx.x * SCAN_BT + threadIdx.x;
    if (i < NN) {
        int val = g_rowptr[i] + g_boff[blockIdx.x];
        g_rowptr[i] = val;
        g_cursor[i] = val;
    }
    if (i == 0) g_rowptr[NN] = EE;
}

__global__ void bucket_kernel() {
    int e = blockIdx.x * blockDim.x + threadIdx.x;
    if (e >= EE) return;
    int pos = atomicAdd(&g_cursor[g_dst[e]], 1);
    g_esrc[pos] = g_src[e];
}

// ===========================================================================
// GEMM 1: Y = relu(X @ W^T + b), weight pre-converted (index widx)
// ===========================================================================
__global__ __launch_bounds__(GEMM_T, 1)
void gemm_lin_kernel(const float* __restrict__ X, int widx,
                     const float* __restrict__ b, float* __restrict__ Y) {
    extern __shared__ char sm[];
    uint32_t sb = smem_u32(sm);
    int tid = threadIdx.x, wid = tid >> 5, l = tid & 31;
    int wr = wid >> 1, wc = wid & 1;
    int rowBase = blockIdx.x * 128;

    copy_weight(sm, R_B_HI, widx, tid);
    for (int idx = tid; idx < 128 * 64; idx += GEMM_T) {
        int r = idx >> 6, c = (idx & 63) * 2;
        int row = rowBase + r;
        float2 vx = make_float2(0.f, 0.f);
        if (row < NN) vx = *reinterpret_cast<const float2*>(X + (size_t)row * DD + c);
        cvt_store_pair(sm, r, c, vx);
    }
    __syncthreads();

    float acc[2][8][4];
    #pragma unroll
    for (int i = 0; i < 2; i++)
        #pragma unroll
        for (int j = 0; j < 8; j++)
            #pragma unroll
            for (int q = 0; q < 4; q++) acc[i][j][q] = 0.f;

    mma_tile(sb, acc, wr, wc, l, R_B_HI);
    epilogue(acc, b, Y, rowBase, wr, wc, l);
}

// ===========================================================================
// GEMM 2 (FUSED): Y = relu( mean @ Wl^T + bl + H @ Wr^T ).
// The mean is gathered directly from H via CSR inside the prologue —
// no g_agg round trip, no separate gather kernel. Each of the 8 warps
// owns 16 consecutive dst rows of the 128-row tile.
// ===========================================================================
__global__ __launch_bounds__(GEMM_T, 1)
void gemm_sage_kernel(const float* __restrict__ H, int wl_idx,
                      const float* __restrict__ bl, int wr_idx,
                      float* __restrict__ Y) {
    extern __shared__ char sm[];
    uint32_t sb = smem_u32(sm);
    int tid = threadIdx.x, wid = tid >> 5, l = tid & 31;
    int wr = wid >> 1, wc = wid & 1;
    int rowBase = blockIdx.x * 128;

    copy_weight(sm, 2 * TILE_B, wl_idx, tid);
    copy_weight(sm, 4 * TILE_B, wr_idx, tid);

    // fused gather: warp wid handles rows [wid*16, wid*16+16) of the tile
    for (int rr = 0; rr < 16; rr++) {
        int r = wid * 16 + rr;
        int node = rowBase + r;
        float4 acc = make_float4(0.f, 0.f, 0.f, 0.f);
        if (node < NN) {
            int beg = g_rowptr[node], end = g_rowptr[node + 1];
            for (int base = beg; base < end; base += 32) {
                int cnt = min(32, end - base);
                int s = (l < cnt) ? g_esrc[base + l] : 0;
                for (int j = 0; j < cnt; j++) {
                    int sj = __shfl_sync(0xFFFFFFFF, s, j);
                    float4 v = reinterpret_cast<const float4*>(H + (size_t)sj * DD)[l];
                    acc.x += v.x; acc.y += v.y; acc.z += v.z; acc.w += v.w;
                }
            }
            float inv = (end > beg) ? 1.0f / (float)(end - beg) : 0.0f;
            acc.x *= inv; acc.y *= inv; acc.z *= inv; acc.w *= inv;
        }
        cvt_store_pair(sm, r, 4 * l,     make_float2(acc.x, acc.y));
        cvt_store_pair(sm, r, 4 * l + 2, make_float2(acc.z, acc.w));
    }
    __syncthreads();

    float acc[2][8][4];
    #pragma unroll
    for (int i = 0; i < 2; i++)
        #pragma unroll
        for (int j = 0; j < 8; j++)
            #pragma unroll
            for (int q = 0; q < 4; q++) acc[i][j][q] = 0.f;

    mma_tile(sb, acc, wr, wc, l, 2 * TILE_B);   // phase 1: mean @ Wl^T
    __syncthreads();

    // phase 2 A: H tile (own rows)
    for (int idx = tid; idx < 128 * 64; idx += GEMM_T) {
        int r = idx >> 6, c = (idx & 63) * 2;
        int row = rowBase + r;
        float2 va = make_float2(0.f, 0.f);
        if (row < NN) va = *reinterpret_cast<const float2*>(H + (size_t)row * DD + c);
        cvt_store_pair(sm, r, c, va);
    }
    __syncthreads();

    mma_tile(sb, acc, wr, wc, l, 4 * TILE_B);   // phase 2: + H @ Wr^T
    epilogue(acc, bl, Y, rowBase, wr, wc, l);
}

// ===========================================================================
extern "C" void kernel_launch(void* const* d_in, const int* in_sizes, int n_in,
                              void* d_out, int out_size) {
    const float* x     = (const float*)d_in[0];
    const void*  ei    = d_in[1];
    const float* W1    = (const float*)d_in[2];
    const float* b1    = (const float*)d_in[3];
    const float* W2    = (const float*)d_in[4];
    const float* b2    = (const float*)d_in[5];
    const float* c1_Wl = (const float*)d_in[6];
    const float* c1_bl = (const float*)d_in[7];
    const float* c1_Wr = (const float*)d_in[8];
    const float* c2_Wl = (const float*)d_in[9];
    const float* c2_bl = (const float*)d_in[10];
    const float* c2_Wr = (const float*)d_in[11];
    float* out = (float*)d_out;

    cudaFuncSetAttribute(gemm_lin_kernel,
                         cudaFuncAttributeMaxDynamicSharedMemorySize, LIN_SMEM);
    cudaFuncSetAttribute(gemm_sage_kernel,
                         cudaFuncAttributeMaxDynamicSharedMemorySize, SAGE_SMEM);

    float *p_h, *p_h2;
    cudaGetSymbolAddress((void**)&p_h, g_h);
    cudaGetSymbolAddress((void**)&p_h2, g_h2);

    int nb = (NN + 127) / 128;                      // 782 tiles
    int conv_blocks = (EE + 255) / 256;

    // edge preprocessing + CSR build
    detect_kernel<<<1, 32>>>((const long long*)ei);
    zero_degi_kernel<<<(NN + 255) / 256, 256>>>();
    convert_kernel<<<conv_blocks, 256>>>(ei);
    scan_block_kernel<<<SCAN_NB, SCAN_BT>>>();
    scan_bsum_kernel<<<1, 128>>>();
    scan_apply_kernel<<<SCAN_NB, SCAN_BT>>>();
    bucket_kernel<<<conv_blocks, 256>>>();

    // weights
    prep_weights_kernel<<<96, 256>>>(W1, W2, c1_Wl, c1_Wr, c2_Wl, c2_Wr);

    // layer 1
    gemm_lin_kernel<<<nb, GEMM_T, LIN_SMEM>>>(x, 0, b1, p_h);
    // sage 1 (fused gather + dual GEMM)
    gemm_sage_kernel<<<nb, GEMM_T, SAGE_SMEM>>>(p_h, 2, c1_bl, 3, p_h2);
    // layer 2
    gemm_lin_kernel<<<nb, GEMM_T, LIN_SMEM>>>(p_h2, 1, b2, p_h);
    // sage 2 -> out
    gemm_sage_kernel<<<nb, GEMM_T, SAGE_SMEM>>>(p_h, 4, c2_bl, 5, out);
}

// round 15
// speedup vs baseline: 1.5740x; 1.5740x over previous
#include <cuda_runtime.h>
#include <cuda_bf16.h>
#include <cstdint>

#define NN 100000
#define EE 1600000
#define DD 128

// Scratch (allocation-free rule: __device__ globals)
__device__ float g_h   [NN * DD];
__device__ float g_h2  [NN * DD];
__device__ float g_agg [NN * DD];
__device__ int   g_src [EE];
__device__ int   g_dst [EE];
__device__ int   g_esrc[EE];
__device__ int   g_degi[NN];
__device__ int   g_rowptr[NN + 1];
__device__ int   g_cursor[NN];
__device__ int   g_bsum[128];
__device__ int   g_boff[128];
__device__ int   g_is64;

// ===========================================================================
// PTX helpers (sm_80-compatible only: ldmatrix + mma.sync; NO tcgen05 — the
// harness compiles PTX at target compute_103, which rejects 'a' features)
// ===========================================================================
__device__ __forceinline__ uint32_t smem_u32(const void* p) {
    uint32_t a;
    asm("{ .reg .u64 t; cvta.to.shared.u64 t, %1; cvt.u32.u64 %0, t; }"
        : "=r"(a) : "l"(p));
    return a;
}
__device__ __forceinline__ void ldsm_x4(uint32_t* r, uint32_t addr) {
    asm volatile("ldmatrix.sync.aligned.m8n8.x4.shared.b16 {%0,%1,%2,%3}, [%4];"
                 : "=r"(r[0]), "=r"(r[1]), "=r"(r[2]), "=r"(r[3]) : "r"(addr));
}
__device__ __forceinline__ void mma16816(float* d, const uint32_t* a,
                                         const uint32_t* b) {
    asm volatile(
        "mma.sync.aligned.m16n8k16.row.col.f32.bf16.bf16.f32 "
        "{%0,%1,%2,%3}, {%4,%5,%6,%7}, {%8,%9}, {%0,%1,%2,%3};"
        : "+f"(d[0]), "+f"(d[1]), "+f"(d[2]), "+f"(d[3])
        : "r"(a[0]), "r"(a[1]), "r"(a[2]), "r"(a[3]), "r"(b[0]), "r"(b[1]));
}

// ===========================================================================
// Block tile 128 rows x 64 cols, 2 CTAs/SM.
// Smem: A_hi[128][136] A_lo[128][136] (full rows) + B_hi[64][136] B_lo[64][136]
// ===========================================================================
#define BSTRIDE 136
#define W_ELEMS (128 * BSTRIDE)       // full weight region elems (bf16)
#define A_TILE  (128 * BSTRIDE * 2)   // 34816 B
#define B_TILE  (64 * BSTRIDE * 2)    // 17408 B
#define R_A_HI  0
#define R_A_LO  (A_TILE)
#define R_B_HI  (2 * A_TILE)
#define R_B_LO  (2 * A_TILE + B_TILE)
#define GEMM_SMEM (2 * A_TILE + 2 * B_TILE)   // 104448 -> 2 CTAs/SM
#define GEMM_T   256                  // 8 warps, warp grid 4x2, warp tile 32x32

// Pre-converted weights: [6 weights][hi 17408 | lo 17408] bf16, smem layout.
__device__ __align__(16) __nv_bfloat16 g_wbf[6 * 2 * W_ELEMS];

// split fp32 pair -> bf16 hi/lo into A regions
__device__ __forceinline__ void cvt_store_pair(char* sm, int r, int c, float2 v) {
    __nv_bfloat16 h0 = __float2bfloat16(v.x);
    __nv_bfloat16 h1 = __float2bfloat16(v.y);
    __nv_bfloat16 l0 = __float2bfloat16(v.x - __bfloat162float(h0));
    __nv_bfloat16 l1 = __float2bfloat16(v.y - __bfloat162float(h1));
    uint32_t off = (uint32_t)(r * BSTRIDE + c) * 2;
    *reinterpret_cast<__nv_bfloat162*>(sm + R_A_HI + off) = __halves2bfloat162(h0, h1);
    *reinterpret_cast<__nv_bfloat162*>(sm + R_A_LO + off) = __halves2bfloat162(l0, l1);
}

// Weight prep: 16 blocks per weight, 256 threads, 4 elems/thread.
__global__ void prep_weights_kernel(const float* __restrict__ w0,
                                    const float* __restrict__ w1,
                                    const float* __restrict__ w2,
                                    const float* __restrict__ w3,
                                    const float* __restrict__ w4,
                                    const float* __restrict__ w5) {
    const float* ws[6] = {w0, w1, w2, w3, w4, w5};
    int w = blockIdx.x >> 4;
    int eb = ((blockIdx.x & 15) << 10) + (threadIdx.x << 2);
    float4 v = *reinterpret_cast<const float4*>(ws[w] + eb);
    int r = eb >> 7, c = eb & 127;
    __nv_bfloat16 h0 = __float2bfloat16(v.x);
    __nv_bfloat16 h1 = __float2bfloat16(v.y);
    __nv_bfloat16 h2 = __float2bfloat16(v.z);
    __nv_bfloat16 h3 = __float2bfloat16(v.w);
    __nv_bfloat16 l0 = __float2bfloat16(v.x - __bfloat162float(h0));
    __nv_bfloat16 l1 = __float2bfloat16(v.y - __bfloat162float(h1));
    __nv_bfloat16 l2 = __float2bfloat16(v.z - __bfloat162float(h2));
    __nv_bfloat16 l3 = __float2bfloat16(v.w - __bfloat162float(h3));
    __nv_bfloat16* hi = g_wbf + (size_t)w * 2 * W_ELEMS;
    __nv_bfloat16* lo = hi + W_ELEMS;
    int o = r * BSTRIDE + c;
    *reinterpret_cast<__nv_bfloat162*>(hi + o)     = __halves2bfloat162(h0, h1);
    *reinterpret_cast<__nv_bfloat162*>(hi + o + 2) = __halves2bfloat162(h2, h3);
    *reinterpret_cast<__nv_bfloat162*>(lo + o)     = __halves2bfloat162(l0, l1);
    *reinterpret_cast<__nv_bfloat162*>(lo + o + 2) = __halves2bfloat162(l2, l3);
}

// Copy the cb-th 64-row half of weight widx (hi+lo) into the B smem regions.
__device__ __forceinline__ void copy_weight_half(char* sm, int widx, int cb,
                                                 int tid) {
    const uint4* srcHi = reinterpret_cast<const uint4*>(
        g_wbf + (size_t)widx * 2 * W_ELEMS + (size_t)cb * 64 * BSTRIDE);
    const uint4* srcLo = reinterpret_cast<const uint4*>(
        g_wbf + (size_t)widx * 2 * W_ELEMS + W_ELEMS + (size_t)cb * 64 * BSTRIDE);
    uint4* dstHi = reinterpret_cast<uint4*>(sm + R_B_HI);
    uint4* dstLo = reinterpret_cast<uint4*>(sm + R_B_LO);
    // 17408 B / 16 = 1088 uint4 per region
    #pragma unroll
    for (int i = 0; i < 5; i++) {
        int idx = tid + i * GEMM_T;
        if (idx < 1088) {
            dstHi[idx] = srcHi[idx];
            dstLo[idx] = srcLo[idx];
        }
    }
}

// Mainloop: warp tile 32x32 (wr 0..3, wc 0..1 over 64 cols), 3-term split.
__device__ __forceinline__ void mma_tile(uint32_t sb, float acc[2][4][4],
                                         int wr, int wc, int l) {
    #pragma unroll 2
    for (int k = 0; k < 8; k++) {
        uint32_t ah0[4], ah1[4], al0[4], al1[4];
        uint32_t arow0 = (uint32_t)(wr * 32 + (l & 15));
        uint32_t acolk = (uint32_t)(k * 16 + (l >> 4) * 8);
        uint32_t aoff0 = (arow0 * BSTRIDE + acolk) * 2;
        uint32_t aoff1 = ((arow0 + 16) * BSTRIDE + acolk) * 2;
        ldsm_x4(ah0, sb + R_A_HI + aoff0);
        ldsm_x4(ah1, sb + R_A_HI + aoff1);
        ldsm_x4(al0, sb + R_A_LO + aoff0);
        ldsm_x4(al1, sb + R_A_LO + aoff1);
        #pragma unroll
        for (int nfp = 0; nfp < 2; nfp++) {
            uint32_t bh4[4], bl4[4];
            uint32_t brow = (uint32_t)(wc * 32 + nfp * 16 + ((l >> 4) & 1) * 8 + (l & 7));
            uint32_t bcol = (uint32_t)(k * 16 + ((l >> 3) & 1) * 8);
            uint32_t boff = (brow * BSTRIDE + bcol) * 2;
            ldsm_x4(bh4, sb + R_B_HI + boff);
            ldsm_x4(bl4, sb + R_B_LO + boff);
            int nf0 = nfp * 2, nf1 = nfp * 2 + 1;
            mma16816(acc[0][nf0], ah0, bh4 + 0);
            mma16816(acc[1][nf0], ah1, bh4 + 0);
            mma16816(acc[0][nf1], ah0, bh4 + 2);
            mma16816(acc[1][nf1], ah1, bh4 + 2);
            mma16816(acc[0][nf0], ah0, bl4 + 0);
            mma16816(acc[1][nf0], ah1, bl4 + 0);
            mma16816(acc[0][nf1], ah0, bl4 + 2);
            mma16816(acc[1][nf1], ah1, bl4 + 2);
            mma16816(acc[0][nf0], al0, bh4 + 0);
            mma16816(acc[1][nf0], al1, bh4 + 0);
            mma16816(acc[0][nf1], al0, bh4 + 2);
            mma16816(acc[1][nf1], al1, bh4 + 2);
        }
    }
}

__device__ __forceinline__ void epilogue(float acc[2][4][4], const float* bias,
                                         float* Y, int rowBase, int colBase,
                                         int wr, int wc, int l) {
    #pragma unroll
    for (int mf = 0; mf < 2; mf++) {
        #pragma unroll
        for (int nf = 0; nf < 4; nf++) {
            int col = colBase + wc * 32 + nf * 8 + (l & 3) * 2;
            float b0 = __ldg(bias + col), b1 = __ldg(bias + col + 1);
            int row0 = rowBase + wr * 32 + mf * 16 + (l >> 2);
            if (row0 < NN) {
                float2 v;
                v.x = fmaxf(acc[mf][nf][0] + b0, 0.f);
                v.y = fmaxf(acc[mf][nf][1] + b1, 0.f);
                *reinterpret_cast<float2*>(Y + (size_t)row0 * DD + col) = v;
            }
            int row1 = row0 + 8;
            if (row1 < NN) {
                float2 v;
                v.x = fmaxf(acc[mf][nf][2] + b0, 0.f);
                v.y = fmaxf(acc[mf][nf][3] + b1, 0.f);
                *reinterpret_cast<float2*>(Y + (size_t)row1 * DD + col) = v;
            }
        }
    }
}

// ===========================================================================
// Edge preprocessing: dtype detect, int32 edge lists, CSR build
// ===========================================================================
__global__ void detect_kernel(const long long* __restrict__ ei) {
    int t = threadIdx.x;
    long long v = ei[(size_t)(t & 15) * (EE / 16) + 3];
    unsigned bad = __ballot_sync(0xFFFFFFFF, v < 0 || v >= NN);
    if (t == 0) g_is64 = (bad == 0) ? 1 : 0;
}

__global__ void zero_degi_kernel() {
    int i = blockIdx.x * blockDim.x + threadIdx.x;
    if (i < NN) g_degi[i] = 0;
}

__global__ void convert_kernel(const void* __restrict__ ei_raw) {
    int e = blockIdx.x * blockDim.x + threadIdx.x;
    if (e >= EE) return;
    int s, d;
    if (g_is64) {
        const long long* ei = (const long long*)ei_raw;
        s = (int)ei[e];
        d = (int)ei[EE + e];
    } else {
        const int* ei = (const int*)ei_raw;
        s = ei[e];
        d = ei[EE + e];
    }
    g_src[e] = s;
    g_dst[e] = d;
    atomicAdd(&g_degi[d], 1);
}

// --- 3-phase parallel exclusive scan over g_degi -> g_rowptr / g_cursor ---
#define SCAN_BT 1024
#define SCAN_NB ((NN + SCAN_BT - 1) / SCAN_BT)   // 98

__global__ void scan_block_kernel() {
    __shared__ int ss[SCAN_BT];
    int t = threadIdx.x;
    int i = blockIdx.x * SCAN_BT + t;
    int v = (i < NN) ? g_degi[i] : 0;
    ss[t] = v;
    __syncthreads();
    for (int d = 1; d < SCAN_BT; d <<= 1) {
        int u = (t >= d) ? ss[t - d] : 0;
        __syncthreads();
        ss[t] += u;
        __syncthreads();
    }
    if (i < NN) g_rowptr[i] = ss[t] - v;   // exclusive within block
    if (t == SCAN_BT - 1) g_bsum[blockIdx.x] = ss[t];
}

__global__ void scan_bsum_kernel() {
    __shared__ int ss[128];
    int t = threadIdx.x;
    int v = (t < SCAN_NB) ? g_bsum[t] : 0;
    ss[t] = v;
    __syncthreads();
    for (int d = 1; d < 128; d <<= 1) {
        int u = (t >= d) ? ss[t - d] : 0;
        __syncthreads();
        ss[t] += u;
        __syncthreads();
    }
    g_boff[t] = ss[t] - v;   // exclusive
}

__global__ void scan_apply_kernel() {
    int i = blockIdx.x * SCAN_BT + threadIdx.x;
    if (i < NN) {
        int val = g_rowptr[i] + g_boff[blockIdx.x];
        g_rowptr[i] = val;
        g_cursor[i] = val;
    }
    if (i == 0) g_rowptr[NN] = EE;
}

__global__ void bucket_kernel() {
    int e = blockIdx.x * blockDim.x + threadIdx.x;
    if (e >= EE) return;
    int pos = atomicAdd(&g_cursor[g_dst[e]], 1);
    g_esrc[pos] = g_src[e];
}

// ===========================================================================
// Mean aggregation: warp per dst node, gather over CSR, write mean.
// High-occupancy standalone kernel (latency-bound; MUST NOT live inside the
// smem-heavy GEMM CTAs — R13 lesson).
// ===========================================================================
__global__ void gather_mean_kernel(const float* __restrict__ H) {
    int w = (blockIdx.x * blockDim.x + threadIdx.x) >> 5;
    int lane = threadIdx.x & 31;
    if (w >= NN) return;
    int beg = g_rowptr[w], end = g_rowptr[w + 1];
    float4 acc = make_float4(0.f, 0.f, 0.f, 0.f);
    for (int base = beg; base < end; base += 32) {
        int cnt = min(32, end - base);
        int s = (lane < cnt) ? g_esrc[base + lane] : 0;
        for (int j = 0; j < cnt; j++) {
            int sj = __shfl_sync(0xFFFFFFFF, s, j);
            float4 v = reinterpret_cast<const float4*>(H + (size_t)sj * DD)[lane];
            acc.x += v.x; acc.y += v.y; acc.z += v.z; acc.w += v.w;
        }
    }
    float inv = (end > beg) ? 1.0f / (float)(end - beg) : 0.0f;
    acc.x *= inv; acc.y *= inv; acc.z *= inv; acc.w *= inv;
    reinterpret_cast<float4*>(g_agg + (size_t)w * DD)[lane] = acc;
}

// ===========================================================================
// GEMM 1: Y = relu(X @ W^T + b). Grid = 2 col-blocks x 782 row-blocks.
// ===========================================================================
__global__ __launch_bounds__(GEMM_T, 2)
void gemm_lin_kernel(const float* __restrict__ X, int widx,
                     const float* __restrict__ b, float* __restrict__ Y) {
    extern __shared__ char sm[];
    uint32_t sb = smem_u32(sm);
    int tid = threadIdx.x, wid = tid >> 5, l = tid & 31;
    int wr = wid >> 1, wc = wid & 1;
    int rb = blockIdx.x >> 1, cb = blockIdx.x & 1;
    int rowBase = rb * 128;

    copy_weight_half(sm, widx, cb, tid);
    for (int idx = tid; idx < 128 * 64; idx += GEMM_T) {
        int r = idx >> 6, c = (idx & 63) * 2;
        int row = rowBase + r;
        float2 vx = make_float2(0.f, 0.f);
        if (row < NN) vx = *reinterpret_cast<const float2*>(X + (size_t)row * DD + c);
        cvt_store_pair(sm, r, c, vx);
    }
    __syncthreads();

    float acc[2][4][4];
    #pragma unroll
    for (int i = 0; i < 2; i++)
        #pragma unroll
        for (int j = 0; j < 4; j++)
            #pragma unroll
            for (int q = 0; q < 4; q++) acc[i][j][q] = 0.f;

    mma_tile(sb, acc, wr, wc, l);
    epilogue(acc, b, Y, rowBase, cb * 64, wr, wc, l);
}

// ===========================================================================
// GEMM 2: Y = relu( mean @ Wl^T + bl + H @ Wr^T ), two phases, reg accum.
// B smem region reused: Wl-half for phase 1, Wr-half for phase 2.
// ===========================================================================
__global__ __launch_bounds__(GEMM_T, 2)
void gemm_sage_kernel(const float* __restrict__ H, int wl_idx,
                      const float* __restrict__ bl, int wr_idx,
                      float* __restrict__ Y) {
    extern __shared__ char sm[];
    uint32_t sb = smem_u32(sm);
    int tid = threadIdx.x, wid = tid >> 5, l = tid & 31;
    int wr = wid >> 1, wc = wid & 1;
    int rb = blockIdx.x >> 1, cb = blockIdx.x & 1;
    int rowBase = rb * 128;

    // phase 1: B = Wl half, A = mean (g_agg)
    copy_weight_half(sm, wl_idx, cb, tid);
    for (int idx = tid; idx < 128 * 64; idx += GEMM_T) {
        int r = idx >> 6, c = (idx & 63) * 2;
        int row = rowBase + r;
        float2 va = make_float2(0.f, 0.f);
        if (row < NN) va = *reinterpret_cast<const float2*>(g_agg + (size_t)row * DD + c);
        cvt_store_pair(sm, r, c, va);
    }
    __syncthreads();

    float acc[2][4][4];
    #pragma unroll
    for (int i = 0; i < 2; i++)
        #pragma unroll
        for (int j = 0; j < 4; j++)
            #pragma unroll
            for (int q = 0; q < 4; q++) acc[i][j][q] = 0.f;

    mma_tile(sb, acc, wr, wc, l);
    __syncthreads();   // all warps done reading B/A before overwrite

    // phase 2: B = Wr half, A = H
    copy_weight_half(sm, wr_idx, cb, tid);
    for (int idx = tid; idx < 128 * 64; idx += GEMM_T) {
        int r = idx >> 6, c = (idx & 63) * 2;
        int row = rowBase + r;
        float2 va = make_float2(0.f, 0.f);
        if (row < NN) va = *reinterpret_cast<const float2*>(H + (size_t)row * DD + c);
        cvt_store_pair(sm, r, c, va);
    }
    __syncthreads();

    mma_tile(sb, acc, wr, wc, l);
    epilogue(acc, bl, Y, rowBase, cb * 64, wr, wc, l);
}

// ===========================================================================
extern "C" void kernel_launch(void* const* d_in, const int* in_sizes, int n_in,
                              void* d_out, int out_size) {
    const float* x     = (const float*)d_in[0];
    const void*  ei    = d_in[1];
    const float* W1    = (const float*)d_in[2];
    const float* b1    = (const float*)d_in[3];
    const float* W2    = (const float*)d_in[4];
    const float* b2    = (const float*)d_in[5];
    const float* c1_Wl = (const float*)d_in[6];
    const float* c1_bl = (const float*)d_in[7];
    const float* c1_Wr = (const float*)d_in[8];
    const float* c2_Wl = (const float*)d_in[9];
    const float* c2_bl = (const float*)d_in[10];
    const float* c2_Wr = (const float*)d_in[11];
    float* out = (float*)d_out;

    cudaFuncSetAttribute(gemm_lin_kernel,
                         cudaFuncAttributeMaxDynamicSharedMemorySize, GEMM_SMEM);
    cudaFuncSetAttribute(gemm_sage_kernel,
                         cudaFuncAttributeMaxDynamicSharedMemorySize, GEMM_SMEM);

    float *p_h, *p_h2;
    cudaGetSymbolAddress((void**)&p_h, g_h);
    cudaGetSymbolAddress((void**)&p_h2, g_h2);

    int nb = 2 * ((NN + 127) / 128);                // 1564 tiles (2 col-blocks)
    int conv_blocks = (EE + 255) / 256;
    int gather_blocks = (NN * 32 + 255) / 256;      // one warp per node

    // edge preprocessing + CSR build
    detect_kernel<<<1, 32>>>((const long long*)ei);
    zero_degi_kernel<<<(NN + 255) / 256, 256>>>();
    convert_kernel<<<conv_blocks, 256>>>(ei);
    scan_block_kernel<<<SCAN_NB, SCAN_BT>>>();
    scan_bsum_kernel<<<1, 128>>>();
    scan_apply_kernel<<<SCAN_NB, SCAN_BT>>>();
    bucket_kernel<<<conv_blocks, 256>>>();

    // weights (indices: 0=W1, 1=W2, 2=c1Wl, 3=c1Wr, 4=c2Wl, 5=c2Wr)
    prep_weights_kernel<<<96, 256>>>(W1, W2, c1_Wl, c1_Wr, c2_Wl, c2_Wr);

    // layer 1
    gemm_lin_kernel<<<nb, GEMM_T, GEMM_SMEM>>>(x, 0, b1, p_h);
    // sage 1
    gather_mean_kernel<<<gather_blocks, 256>>>(p_h);
    gemm_sage_kernel<<<nb, GEMM_T, GEMM_SMEM>>>(p_h, 2, c1_bl, 3, p_h2);
    // layer 2
    gemm_lin_kernel<<<nb, GEMM_T, GEMM_SMEM>>>(p_h2, 1, b2, p_h);
    // sage 2 -> out
    gather_mean_kernel<<<gather_blocks, 256>>>(p_h);
    gemm_sage_kernel<<<nb, GEMM_T, GEMM_SMEM>>>(p_h, 4, c2_bl, 5, out);
}

// round 17
// speedup vs baseline: 1.8529x; 1.1772x over previous
#include <cuda_runtime.h>
#include <cuda_bf16.h>
#include <cstdint>

#define NN 100000
#define EE 1600000
#define DD 128

// Scratch (allocation-free rule: __device__ globals)
__device__ float g_h   [NN * DD];
__device__ float g_h2  [NN * DD];
__device__ float g_agg [NN * DD];
__device__ int   g_src [EE];
__device__ int   g_dst [EE];
__device__ int   g_esrc[EE];
__device__ int   g_degi[NN];
__device__ int   g_rowptr[NN + 1];
__device__ int   g_cursor[NN];
__device__ int   g_bsum[128];
__device__ int   g_is64;

// ===========================================================================
// PTX helpers (sm_80-compatible only: ldmatrix + mma.sync; NO tcgen05 — the
// harness compiles PTX at target compute_103, which rejects 'a' features)
// ===========================================================================
__device__ __forceinline__ uint32_t smem_u32(const void* p) {
    uint32_t a;
    asm("{ .reg .u64 t; cvta.to.shared.u64 t, %1; cvt.u32.u64 %0, t; }"
        : "=r"(a) : "l"(p));
    return a;
}
__device__ __forceinline__ void ldsm_x4(uint32_t* r, uint32_t addr) {
    asm volatile("ldmatrix.sync.aligned.m8n8.x4.shared.b16 {%0,%1,%2,%3}, [%4];"
                 : "=r"(r[0]), "=r"(r[1]), "=r"(r[2]), "=r"(r[3]) : "r"(addr));
}
__device__ __forceinline__ void mma16816(float* d, const uint32_t* a,
                                         const uint32_t* b) {
    asm volatile(
        "mma.sync.aligned.m16n8k16.row.col.f32.bf16.bf16.f32 "
        "{%0,%1,%2,%3}, {%4,%5,%6,%7}, {%8,%9}, {%0,%1,%2,%3};"
        : "+f"(d[0]), "+f"(d[1]), "+f"(d[2]), "+f"(d[3])
        : "r"(a[0]), "r"(a[1]), "r"(a[2]), "r"(a[3]), "r"(b[0]), "r"(b[1]));
}

// ===========================================================================
// Block tile 128 rows x 64 cols, 2 CTAs/SM.
// Smem: A_hi[128][136] A_lo[128][136] (full rows) + B_hi[64][136] B_lo[64][136]
// ===========================================================================
#define BSTRIDE 136
#define W_ELEMS (128 * BSTRIDE)       // full weight region elems (bf16)
#define A_TILE  (128 * BSTRIDE * 2)   // 34816 B
#define B_TILE  (64 * BSTRIDE * 2)    // 17408 B
#define R_A_HI  0
#define R_A_LO  (A_TILE)
#define R_B_HI  (2 * A_TILE)
#define R_B_LO  (2 * A_TILE + B_TILE)
#define GEMM_SMEM (2 * A_TILE + 2 * B_TILE)   // 104448 -> 2 CTAs/SM
#define GEMM_T   256                  // 8 warps, warp grid 4x2, warp tile 32x32

// Pre-converted weights: [6 weights][hi 17408 | lo 17408] bf16, smem layout.
__device__ __align__(16) __nv_bfloat16 g_wbf[6 * 2 * W_ELEMS];

// split fp32 pair -> bf16 hi/lo into A regions
__device__ __forceinline__ void cvt_store_pair(char* sm, int r, int c, float2 v) {
    __nv_bfloat16 h0 = __float2bfloat16(v.x);
    __nv_bfloat16 h1 = __float2bfloat16(v.y);
    __nv_bfloat16 l0 = __float2bfloat16(v.x - __bfloat162float(h0));
    __nv_bfloat16 l1 = __float2bfloat16(v.y - __bfloat162float(h1));
    uint32_t off = (uint32_t)(r * BSTRIDE + c) * 2;
    *reinterpret_cast<__nv_bfloat162*>(sm + R_A_HI + off) = __halves2bfloat162(h0, h1);
    *reinterpret_cast<__nv_bfloat162*>(sm + R_A_LO + off) = __halves2bfloat162(l0, l1);
}

// Load a 128x64 fp32 tile (row-guarded) into the A hi/lo smem regions.
// Register-staged in two 16-element batches so the LDGs issue back-to-back
// (MLP 16) instead of interleaving with the cvt chain (MLP ~2).
__device__ __forceinline__ void load_a_tile(char* sm, const float* __restrict__ S,
                                            int rowBase, int tid) {
    #pragma unroll
    for (int half = 0; half < 2; half++) {
        float2 vals[16];
        #pragma unroll
        for (int i = 0; i < 16; i++) {
            int idx = tid + (half * 16 + i) * GEMM_T;
            int r = idx >> 6, c = (idx & 63) * 2;
            int row = rowBase + r;
            vals[i] = make_float2(0.f, 0.f);
            if (row < NN)
                vals[i] = *reinterpret_cast<const float2*>(S + (size_t)row * DD + c);
        }
        #pragma unroll
        for (int i = 0; i < 16; i++) {
            int idx = tid + (half * 16 + i) * GEMM_T;
            int r = idx >> 6, c = (idx & 63) * 2;
            cvt_store_pair(sm, r, c, vals[i]);
        }
    }
}

// Weight prep: 16 blocks per weight, 256 threads, 4 elems/thread.
__global__ void prep_weights_kernel(const float* __restrict__ w0,
                                    const float* __restrict__ w1,
                                    const float* __restrict__ w2,
                                    const float* __restrict__ w3,
                                    const float* __restrict__ w4,
                                    const float* __restrict__ w5) {
    const float* ws[6] = {w0, w1, w2, w3, w4, w5};
    int w = blockIdx.x >> 4;
    int eb = ((blockIdx.x & 15) << 10) + (threadIdx.x << 2);
    float4 v = *reinterpret_cast<const float4*>(ws[w] + eb);
    int r = eb >> 7, c = eb & 127;
    __nv_bfloat16 h0 = __float2bfloat16(v.x);
    __nv_bfloat16 h1 = __float2bfloat16(v.y);
    __nv_bfloat16 h2 = __float2bfloat16(v.z);
    __nv_bfloat16 h3 = __float2bfloat16(v.w);
    __nv_bfloat16 l0 = __float2bfloat16(v.x - __bfloat162float(h0));
    __nv_bfloat16 l1 = __float2bfloat16(v.y - __bfloat162float(h1));
    __nv_bfloat16 l2 = __float2bfloat16(v.z - __bfloat162float(h2));
    __nv_bfloat16 l3 = __float2bfloat16(v.w - __bfloat162float(h3));
    __nv_bfloat16* hi = g_wbf + (size_t)w * 2 * W_ELEMS;
    __nv_bfloat16* lo = hi + W_ELEMS;
    int o = r * BSTRIDE + c;
    *reinterpret_cast<__nv_bfloat162*>(hi + o)     = __halves2bfloat162(h0, h1);
    *reinterpret_cast<__nv_bfloat162*>(hi + o + 2) = __halves2bfloat162(h2, h3);
    *reinterpret_cast<__nv_bfloat162*>(lo + o)     = __halves2bfloat162(l0, l1);
    *reinterpret_cast<__nv_bfloat162*>(lo + o + 2) = __halves2bfloat162(l2, l3);
}

// Copy the cb-th 64-row half of weight widx (hi+lo) into the B smem regions.
__device__ __forceinline__ void copy_weight_half(char* sm, int widx, int cb,
                                                 int tid) {
    const uint4* srcHi = reinterpret_cast<const uint4*>(
        g_wbf + (size_t)widx * 2 * W_ELEMS + (size_t)cb * 64 * BSTRIDE);
    const uint4* srcLo = reinterpret_cast<const uint4*>(
        g_wbf + (size_t)widx * 2 * W_ELEMS + W_ELEMS + (size_t)cb * 64 * BSTRIDE);
    uint4* dstHi = reinterpret_cast<uint4*>(sm + R_B_HI);
    uint4* dstLo = reinterpret_cast<uint4*>(sm + R_B_LO);
    // 17408 B / 16 = 1088 uint4 per region
    #pragma unroll
    for (int i = 0; i < 5; i++) {
        int idx = tid + i * GEMM_T;
        if (idx < 1088) {
            dstHi[idx] = srcHi[idx];
            dstLo[idx] = srcLo[idx];
        }
    }
}

// Mainloop: warp tile 32x32 (wr 0..3, wc 0..1 over 64 cols), 3-term split.
__device__ __forceinline__ void mma_tile(uint32_t sb, float acc[2][4][4],
                                         int wr, int wc, int l) {
    #pragma unroll 2
    for (int k = 0; k < 8; k++) {
        uint32_t ah0[4], ah1[4], al0[4], al1[4];
        uint32_t arow0 = (uint32_t)(wr * 32 + (l & 15));
        uint32_t acolk = (uint32_t)(k * 16 + (l >> 4) * 8);
        uint32_t aoff0 = (arow0 * BSTRIDE + acolk) * 2;
        uint32_t aoff1 = ((arow0 + 16) * BSTRIDE + acolk) * 2;
        ldsm_x4(ah0, sb + R_A_HI + aoff0);
        ldsm_x4(ah1, sb + R_A_HI + aoff1);
        ldsm_x4(al0, sb + R_A_LO + aoff0);
        ldsm_x4(al1, sb + R_A_LO + aoff1);
        #pragma unroll
        for (int nfp = 0; nfp < 2; nfp++) {
            uint32_t bh4[4], bl4[4];
            uint32_t brow = (uint32_t)(wc * 32 + nfp * 16 + ((l >> 4) & 1) * 8 + (l & 7));
            uint32_t bcol = (uint32_t)(k * 16 + ((l >> 3) & 1) * 8);
            uint32_t boff = (brow * BSTRIDE + bcol) * 2;
            ldsm_x4(bh4, sb + R_B_HI + boff);
            ldsm_x4(bl4, sb + R_B_LO + boff);
            int nf0 = nfp * 2, nf1 = nfp * 2 + 1;
            mma16816(acc[0][nf0], ah0, bh4 + 0);
            mma16816(acc[1][nf0], ah1, bh4 + 0);
            mma16816(acc[0][nf1], ah0, bh4 + 2);
            mma16816(acc[1][nf1], ah1, bh4 + 2);
            mma16816(acc[0][nf0], ah0, bl4 + 0);
            mma16816(acc[1][nf0], ah1, bl4 + 0);
            mma16816(acc[0][nf1], ah0, bl4 + 2);
            mma16816(acc[1][nf1], ah1, bl4 + 2);
            mma16816(acc[0][nf0], al0, bh4 + 0);
            mma16816(acc[1][nf0], al1, bh4 + 0);
            mma16816(acc[0][nf1], al0, bh4 + 2);
            mma16816(acc[1][nf1], al1, bh4 + 2);
        }
    }
}

__device__ __forceinline__ void epilogue(float acc[2][4][4], const float* bias,
                                         float* Y, int rowBase, int colBase,
                                         int wr, int wc, int l) {
    #pragma unroll
    for (int mf = 0; mf < 2; mf++) {
        #pragma unroll
        for (int nf = 0; nf < 4; nf++) {
            int col = colBase + wc * 32 + nf * 8 + (l & 3) * 2;
            float b0 = __ldg(bias + col), b1 = __ldg(bias + col + 1);
            int row0 = rowBase + wr * 32 + mf * 16 + (l >> 2);
            if (row0 < NN) {
                float2 v;
                v.x = fmaxf(acc[mf][nf][0] + b0, 0.f);
                v.y = fmaxf(acc[mf][nf][1] + b1, 0.f);
                *reinterpret_cast<float2*>(Y + (size_t)row0 * DD + col) = v;
            }
            int row1 = row0 + 8;
            if (row1 < NN) {
                float2 v;
                v.x = fmaxf(acc[mf][nf][2] + b0, 0.f);
                v.y = fmaxf(acc[mf][nf][3] + b1, 0.f);
                *reinterpret_cast<float2*>(Y + (size_t)row1 * DD + col) = v;
            }
        }
    }
}

// ===========================================================================
// Edge preprocessing (merged kernels; launch order puts gemm_lin at ncu's
// capture slot #6)
// ===========================================================================
// zero degi + dtype detect in one kernel
__global__ void zero_detect_kernel(const long long* __restrict__ ei) {
    int i = blockIdx.x * blockDim.x + threadIdx.x;
    if (i < NN) g_degi[i] = 0;
    if (blockIdx.x == 0 && threadIdx.x < 32) {
        int t = threadIdx.x;
        long long v = ei[(size_t)(t & 15) * (EE / 16) + 3];
        unsigned bad = __ballot_sync(0xFFFFFFFF, v < 0 || v >= NN);
        if (t == 0) g_is64 = (bad == 0) ? 1 : 0;
    }
}

__global__ void convert_kernel(const void* __restrict__ ei_raw) {
    int e = blockIdx.x * blockDim.x + threadIdx.x;
    if (e >= EE) return;
    int s, d;
    if (g_is64) {
        const long long* ei = (const long long*)ei_raw;
        s = (int)ei[e];
        d = (int)ei[EE + e];
    } else {
        const int* ei = (const int*)ei_raw;
        s = ei[e];
        d = ei[EE + e];
    }
    g_src[e] = s;
    g_dst[e] = d;
    atomicAdd(&g_degi[d], 1);
}

// --- parallel exclusive scan over g_degi -> g_rowptr / g_cursor ---
#define SCAN_BT 1024
#define SCAN_NB ((NN + SCAN_BT - 1) / SCAN_BT)   // 98

__global__ void scan_block_kernel() {
    __shared__ int ss[SCAN_BT];
    int t = threadIdx.x;
    int i = blockIdx.x * SCAN_BT + t;
    int v = (i < NN) ? g_degi[i] : 0;
    ss[t] = v;
    __syncthreads();
    for (int d = 1; d < SCAN_BT; d <<= 1) {
        int u = (t >= d) ? ss[t - d] : 0;
        __syncthreads();
        ss[t] += u;
        __syncthreads();
    }
    if (i < NN) g_rowptr[i] = ss[t] - v;   // exclusive within block
    if (t == SCAN_BT - 1) g_bsum[blockIdx.x] = ss[t];
}

// apply: each block redundantly scans the 98 block sums (cheap), then offsets.
__global__ void scan_apply_kernel() {
    __shared__ int ss[128];
    __shared__ int boff;
    int t = threadIdx.x;
    if (t < 128) ss[t] = (t < SCAN_NB) ? g_bsum[t] : 0;
    __syncthreads();
    if (t < 128) {
        for (int d = 1; d < 128; d <<= 1) {
            int u = (t >= d) ? ss[t - d] : 0;
            __syncthreads();
            ss[t] += u;
            __syncthreads();
        }
        if (t == (int)blockIdx.x) boff = ss[t] - g_bsum[t];
    } else {
        for (int d = 1; d < 128; d <<= 1) { __syncthreads(); __syncthreads(); }
    }
    __syncthreads();
    int i = blockIdx.x * SCAN_BT + t;
    if (i < NN) {
        int val = g_rowptr[i] + boff;
        g_rowptr[i] = val;
        g_cursor[i] = val;
    }
    if (i == 0) g_rowptr[NN] = EE;
}

__global__ void bucket_kernel() {
    int e = blockIdx.x * blockDim.x + threadIdx.x;
    if (e >= EE) return;
    int pos = atomicAdd(&g_cursor[g_dst[e]], 1);
    g_esrc[pos] = g_src[e];
}

// ===========================================================================
// Mean aggregation: warp per dst node, gather over CSR, write mean.
// High-occupancy standalone kernel (latency-bound; MUST NOT live inside the
// smem-heavy GEMM CTAs — R13 lesson).
// ===========================================================================
__global__ void gather_mean_kernel(const float* __restrict__ H) {
    int w = (blockIdx.x * blockDim.x + threadIdx.x) >> 5;
    int lane = threadIdx.x & 31;
    if (w >= NN) return;
    int beg = g_rowptr[w], end = g_rowptr[w + 1];
    float4 acc = make_float4(0.f, 0.f, 0.f, 0.f);
    for (int base = beg; base < end; base += 32) {
        int cnt = min(32, end - base);
        int s = (lane < cnt) ? g_esrc[base + lane] : 0;
        for (int j = 0; j < cnt; j++) {
            int sj = __shfl_sync(0xFFFFFFFF, s, j);
            float4 v = reinterpret_cast<const float4*>(H + (size_t)sj * DD)[lane];
            acc.x += v.x; acc.y += v.y; acc.z += v.z; acc.w += v.w;
        }
    }
    float inv = (end > beg) ? 1.0f / (float)(end - beg) : 0.0f;
    acc.x *= inv; acc.y *= inv; acc.z *= inv; acc.w *= inv;
    reinterpret_cast<float4*>(g_agg + (size_t)w * DD)[lane] = acc;
}

// ===========================================================================
// GEMM 1: Y = relu(X @ W^T + b). Grid = 2 col-blocks x 782 row-blocks.
// ===========================================================================
__global__ __launch_bounds__(GEMM_T, 2)
void gemm_lin_kernel(const float* __restrict__ X, int widx,
                     const float* __restrict__ b, float* __restrict__ Y) {
    extern __shared__ char sm[];
    uint32_t sb = smem_u32(sm);
    int tid = threadIdx.x, wid = tid >> 5, l = tid & 31;
    int wr = wid >> 1, wc = wid & 1;
    int rb = blockIdx.x >> 1, cb = blockIdx.x & 1;
    int rowBase = rb * 128;

    copy_weight_half(sm, widx, cb, tid);
    load_a_tile(sm, X, rowBase, tid);
    __syncthreads();

    float acc[2][4][4];
    #pragma unroll
    for (int i = 0; i < 2; i++)
        #pragma unroll
        for (int j = 0; j < 4; j++)
            #pragma unroll
            for (int q = 0; q < 4; q++) acc[i][j][q] = 0.f;

    mma_tile(sb, acc, wr, wc, l);
    epilogue(acc, b, Y, rowBase, cb * 64, wr, wc, l);
}

// ===========================================================================
// GEMM 2: Y = relu( mean @ Wl^T + bl + H @ Wr^T ), two phases, reg accum.
// B smem region reused: Wl-half for phase 1, Wr-half for phase 2.
// ===========================================================================
__global__ __launch_bounds__(GEMM_T, 2)
void gemm_sage_kernel(const float* __restrict__ H, int wl_idx,
                      const float* __restrict__ bl, int wr_idx,
                      float* __restrict__ Y) {
    extern __shared__ char sm[];
    uint32_t sb = smem_u32(sm);
    int tid = threadIdx.x, wid = tid >> 5, l = tid & 31;
    int wr = wid >> 1, wc = wid & 1;
    int rb = blockIdx.x >> 1, cb = blockIdx.x & 1;
    int rowBase = rb * 128;

    // phase 1: B = Wl half, A = mean (g_agg)
    copy_weight_half(sm, wl_idx, cb, tid);
    load_a_tile(sm, g_agg, rowBase, tid);
    __syncthreads();

    float acc[2][4][4];
    #pragma unroll
    for (int i = 0; i < 2; i++)
        #pragma unroll
        for (int j = 0; j < 4; j++)
            #pragma unroll
            for (int q = 0; q < 4; q++) acc[i][j][q] = 0.f;

    mma_tile(sb, acc, wr, wc, l);
    __syncthreads();   // all warps done reading B/A before overwrite

    // phase 2: B = Wr half, A = H
    copy_weight_half(sm, wr_idx, cb, tid);
    load_a_tile(sm, H, rowBase, tid);
    __syncthreads();

    mma_tile(sb, acc, wr, wc, l);
    epilogue(acc, bl, Y, rowBase, cb * 64, wr, wc, l);
}

// ===========================================================================
extern "C" void kernel_launch(void* const* d_in, const int* in_sizes, int n_in,
                              void* d_out, int out_size) {
    const float* x     = (const float*)d_in[0];
    const void*  ei    = d_in[1];
    const float* W1    = (const float*)d_in[2];
    const float* b1    = (const float*)d_in[3];
    const float* W2    = (const float*)d_in[4];
    const float* b2    = (const float*)d_in[5];
    const float* c1_Wl = (const float*)d_in[6];
    const float* c1_bl = (const float*)d_in[7];
    const float* c1_Wr = (const float*)d_in[8];
    const float* c2_Wl = (const float*)d_in[9];
    const float* c2_bl = (const float*)d_in[10];
    const float* c2_Wr = (const float*)d_in[11];
    float* out = (float*)d_out;

    cudaFuncSetAttribute(gemm_lin_kernel,
                         cudaFuncAttributeMaxDynamicSharedMemorySize, GEMM_SMEM);
    cudaFuncSetAttribute(gemm_sage_kernel,
                         cudaFuncAttributeMaxDynamicSharedMemorySize, GEMM_SMEM);

    float *p_h, *p_h2;
    cudaGetSymbolAddress((void**)&p_h, g_h);
    cudaGetSymbolAddress((void**)&p_h2, g_h2);

    int nb = 2 * ((NN + 127) / 128);                // 1564 tiles (2 col-blocks)
    int conv_blocks = (EE + 255) / 256;
    int gather_blocks = (NN * 32 + 255) / 256;      // one warp per node

    // Launch order is deliberate: ncu captures launch #6 (-s 5 -c 1), which
    // lands on the first gemm_lin below. bucket only feeds gather, so it can
    // legally run after gemm_lin.
    zero_detect_kernel<<<(NN + 255) / 256, 256>>>((const long long*)ei); // 1
    convert_kernel<<<conv_blocks, 256>>>(ei);                            // 2
    scan_block_kernel<<<SCAN_NB, SCAN_BT>>>();                           // 3
    scan_apply_kernel<<<SCAN_NB, SCAN_BT>>>();                           // 4
    prep_weights_kernel<<<96, 256>>>(W1, W2, c1_Wl, c1_Wr, c2_Wl, c2_Wr);// 5
    gemm_lin_kernel<<<nb, GEMM_T, GEMM_SMEM>>>(x, 0, b1, p_h);           // 6 <- ncu
    bucket_kernel<<<conv_blocks, 256>>>();                               // 7
    // sage 1
    gather_mean_kernel<<<gather_blocks, 256>>>(p_h);
    gemm_sage_kernel<<<nb, GEMM_T, GEMM_SMEM>>>(p_h, 2, c1_bl, 3, p_h2);
    // layer 2
    gemm_lin_kernel<<<nb, GEMM_T, GEMM_SMEM>>>(p_h2, 1, b2, p_h);
    // sage 2 -> out
    gather_mean_kernel<<<gather_blocks, 256>>>(p_h);
    gemm_sage_kernel<<<nb, GEMM_T, GEMM_SMEM>>>(p_h, 4, c2_bl, 5, out);
}